// round 1
// baseline (speedup 1.0000x reference)
#include <cuda_runtime.h>

#define BATCH 32768

// One warp per batch element. State = 256 complex amplitudes, 8 per lane:
// amplitude index k = lane*8 + r  (bits 7..3 = lane, bits 2..0 = r).
// Qubit q corresponds to bit (7-q) of k.
//
// CNOT chains are eliminated: they are GF(2)-linear index maps F (F(j)_i =
// j_i ^ j_{i+1}); we keep the stored array fixed and track G = F^-L.
// RX on true bit b becomes an XOR-mask pairing with mask G^-1 e_b:
//   layer 1 masks: F e_b   = (1<<b) | (1<<(b-1))
//   layer 2 masks: F^2 e_b = (1<<b) | (1<<(b-2))
// RX is symmetric, so pair orientation is irrelevant.
// Final PauliZ sign for output qubit i (bit b=7-i): parity(row_b(F^-2) & k),
// row_b(F^-2) = bits {b, b+2, b+4, ...}.

template<int M>
__device__ __forceinline__ void apply_rx(float (&x)[8], float (&y)[8], float c, float s) {
    constexpr int LM  = M >> 3;   // lane-bit part of pair mask
    constexpr int LOC = M & 7;    // local-bit part
    float px[8], py[8];
#pragma unroll
    for (int r = 0; r < 8; r++) { px[r] = x[r ^ LOC]; py[r] = y[r ^ LOC]; }
    if (LM) {
#pragma unroll
        for (int r = 0; r < 8; r++) {
            px[r] = __shfl_xor_sync(0xffffffffu, px[r], LM);
            py[r] = __shfl_xor_sync(0xffffffffu, py[r], LM);
        }
    }
    // new_a[k] = c*a[k] - i*s*a[k^m]  =>  (all-real arithmetic)
    // new_x = c*x + s*py_partner ; new_y = c*y - s*px_partner
#pragma unroll
    for (int r = 0; r < 8; r++) {
        float nx = fmaf(c, x[r],  s * py[r]);
        float ny = fmaf(c, y[r], -s * px[r]);
        x[r] = nx; y[r] = ny;
    }
}

__global__ __launch_bounds__(256) void vqc_kernel(const float* __restrict__ inputs,
                                                  const float* __restrict__ weights,
                                                  float* __restrict__ out) {
    // per-block weight cos/sin (16 angles, shared by all states)
    __shared__ float wc[16], ws[16];
    if (threadIdx.x < 16) {
        float s, c;
        sincosf(0.5f * weights[threadIdx.x], &s, &c);
        ws[threadIdx.x] = s; wc[threadIdx.x] = c;
    }
    __syncthreads();

    const int warp = (blockIdx.x * blockDim.x + threadIdx.x) >> 5;
    const int lane = threadIdx.x & 31;

    // --- RY(z) encoding of |0...0> : product state, purely real ---
    float zq = 0.0f;
    if (lane < 8) zq = inputs[warp * 8 + lane];   // lane q holds angle of qubit q
    float sq, cq;
    sincosf(0.5f * zq, &sq, &cq);

    float cb[8], sb[8];  // indexed by bit b (qubit 7-b)
#pragma unroll
    for (int b = 0; b < 8; b++) {
        cb[b] = __shfl_sync(0xffffffffu, cq, 7 - b);
        sb[b] = __shfl_sync(0xffffffffu, sq, 7 - b);
    }

    float lp = 1.0f;   // product over lane bits (k bits 3..7)
#pragma unroll
    for (int b = 3; b < 8; b++) lp *= ((lane >> (b - 3)) & 1) ? sb[b] : cb[b];

    float x[8], y[8];
#pragma unroll
    for (int r = 0; r < 8; r++) {
        float p = lp * ((r & 4) ? sb[2] : cb[2]);
        p *= ((r & 2) ? sb[1] : cb[1]);
        p *= ((r & 1) ? sb[0] : cb[0]);
        x[r] = p;
        y[r] = 0.0f;
    }

    // --- layer 0: CNOT chain absorbed into masks F*e_b ; weight idx = 7-b ---
    apply_rx<0x01>(x, y, wc[7], ws[7]);
    apply_rx<0x03>(x, y, wc[6], ws[6]);
    apply_rx<0x06>(x, y, wc[5], ws[5]);
    apply_rx<0x0C>(x, y, wc[4], ws[4]);
    apply_rx<0x18>(x, y, wc[3], ws[3]);
    apply_rx<0x30>(x, y, wc[2], ws[2]);
    apply_rx<0x60>(x, y, wc[1], ws[1]);
    apply_rx<0xC0>(x, y, wc[0], ws[0]);
    // --- layer 1: masks F^2*e_b ; weight idx = 8 + (7-b) ---
    apply_rx<0x01>(x, y, wc[15], ws[15]);
    apply_rx<0x02>(x, y, wc[14], ws[14]);
    apply_rx<0x05>(x, y, wc[13], ws[13]);
    apply_rx<0x0A>(x, y, wc[12], ws[12]);
    apply_rx<0x14>(x, y, wc[11], ws[11]);
    apply_rx<0x28>(x, y, wc[10], ws[10]);
    apply_rx<0x50>(x, y, wc[9],  ws[9]);
    apply_rx<0xA0>(x, y, wc[8],  ws[8]);

    // --- PauliZ expectations: sign = parity(A[i] & k), A = row_{7-i}(F^-2) ---
    float p[8];
#pragma unroll
    for (int r = 0; r < 8; r++) p[r] = fmaf(x[r], x[r], y[r] * y[r]);

    constexpr int A[8] = {0x80, 0x40, 0xA0, 0x50, 0xA8, 0x54, 0xAA, 0x55};
#pragma unroll
    for (int i = 0; i < 8; i++) {
        float acc = 0.0f;
#pragma unroll
        for (int r = 0; r < 8; r++)
            acc += (__popc(A[i] & r) & 1) ? -p[r] : p[r];
        if (__popc((A[i] >> 3) & lane) & 1) acc = -acc;
#pragma unroll
        for (int off = 16; off > 0; off >>= 1)
            acc += __shfl_xor_sync(0xffffffffu, acc, off);
        if (lane == i) out[warp * 8 + i] = acc;
    }
}

extern "C" void kernel_launch(void* const* d_in, const int* in_sizes, int n_in,
                              void* d_out, int out_size) {
    const float* inputs  = (const float*)d_in[0];   // (32768, 8) float32
    const float* weights = (const float*)d_in[1];   // (2, 8)     float32
    float* out = (float*)d_out;                     // (32768, 8) float32
    // 32768 warps, 8 warps per 256-thread block -> 4096 blocks (exact fit)
    vqc_kernel<<<BATCH / 8, 256>>>(inputs, weights, out);
}

// round 2
// speedup vs baseline: 1.6162x; 1.6162x over previous
#include <cuda_runtime.h>

#define BATCH 32768
#define FULL 0xffffffffu

// Walsh-domain VQC evaluation.
//
// Stored-state bit convention (validated by the previous passing kernel):
// qubit q <-> bit (7-q). Gates after encoding are c*I - i*s*P_m with masks
//   layer0: m_b = (1<<b)|(1<<(b-1)) (b=0..7, weight w0[7-b])
//   layer1: m_b = (1<<b)|(1<<(b-2)) (weight w1[7-b])
// All P_m are diagonalized by the (unnormalized) Walsh transform:
//   psi_hat[w] = prod_b (c_b + (-1)^{w_b} s_b)     (real, closed form)
//   gate -> phase exp(-i*eps*theta/2), eps = (-1)^popc(m&w)
// Measurement masks A_i (row_{7-i} of F^-2 in stored coords):
//   A = {0x80,0x40,0xA0,0x50,0xA8,0x54,0xAA,0x55}
//   <out_i> = (1/256) sum_w ( u_w u_{w^A} + v_w v_{w^A} ),
//   u = r*cos(phi), v = r*sin(phi), phi_w = 0.5*sum_j eps_j(w)*theta_j.
//
// Layout: 1 warp per state, w = lane*8 + r (8 Walsh coeffs per lane).
// Phase table (weights-only) built once per block in smem, transposed
// layout tab[(w&7)*32 + (w>>3)] for conflict-free per-r loads; values
// pre-scaled by 1/16 so u*u' products carry the 1/256 normalization.

__global__ __launch_bounds__(256) void vqc_walsh_kernel(const float* __restrict__ inputs,
                                                        const float* __restrict__ weights,
                                                        float* __restrict__ out) {
    __shared__ float2 tab[256];

    // ---- per-block phase table: thread t computes Walsh index w = t ----
    {
        const int w = threadIdx.x;
        const int msk[16]  = {0x01,0x03,0x06,0x0C,0x18,0x30,0x60,0xC0,
                              0x01,0x02,0x05,0x0A,0x14,0x28,0x50,0xA0};
        const int widx[16] = {7,6,5,4,3,2,1,0, 15,14,13,12,11,10,9,8};
        float phi = 0.0f;
#pragma unroll
        for (int j = 0; j < 16; j++) {
            float t = __ldg(&weights[widx[j]]);
            phi += (__popc(msk[j] & w) & 1) ? -t : t;
        }
        phi *= 0.5f;
        float sp, cp;
        sincosf(phi, &sp, &cp);
        tab[(w & 7) * 32 + (w >> 3)] = make_float2(cp * 0.0625f, sp * 0.0625f);
    }
    __syncthreads();

    const int warp = (blockIdx.x * blockDim.x + threadIdx.x) >> 5;
    const int lane = threadIdx.x & 31;

    // ---- RY encoding, directly in Walsh domain ----
    float zq = (lane < 8) ? inputs[warp * 8 + lane] : 0.0f;
    float sq, cq;
    sincosf(0.5f * zq, &sq, &cq);
    float plv = cq + sq;   // factor when w_b = 0
    float mlv = cq - sq;   // factor when w_b = 1

    float pb[8], mb[8];    // indexed by bit b; qubit q=7-b lives in lane q
#pragma unroll
    for (int b = 0; b < 8; b++) {
        pb[b] = __shfl_sync(FULL, plv, 7 - b);
        mb[b] = __shfl_sync(FULL, mlv, 7 - b);
    }

    // lane covers w bits 3..7 (lane bits 0..4)
    float lp = ((lane & 1)  ? mb[3] : pb[3]);
    lp      *= ((lane & 2)  ? mb[4] : pb[4]);
    lp      *= ((lane & 4)  ? mb[5] : pb[5]);
    lp      *= ((lane & 8)  ? mb[6] : pb[6]);
    lp      *= ((lane & 16) ? mb[7] : pb[7]);

    float e2p = lp  * pb[2], e2m = lp  * mb[2];
    float rpp = e2p * pb[1], rpm = e2p * mb[1];
    float rmp = e2m * pb[1], rmm = e2m * mb[1];

    float rw[8];
    rw[0] = rpp * pb[0]; rw[1] = rpp * mb[0];
    rw[2] = rpm * pb[0]; rw[3] = rpm * mb[0];
    rw[4] = rmp * pb[0]; rw[5] = rmp * mb[0];
    rw[6] = rmm * pb[0]; rw[7] = rmm * mb[0];

    // ---- apply phases: z_w = r_w * (cos, sin)/16 ----
    float u[8], v[8];
#pragma unroll
    for (int r = 0; r < 8; r++) {
        float2 t = tab[r * 32 + lane];
        u[r] = rw[r] * t.x;
        v[r] = rw[r] * t.y;
    }

    // ---- cross-correlations: 5 distinct lane masks cover all 8 outputs ----
    float a[8];
#pragma unroll
    for (int i = 0; i < 8; i++) a[i] = 0.0f;

    // L=0x10 -> out0 (A=0x80, loc 0)
#pragma unroll
    for (int r = 0; r < 8; r++) {
        float pu = __shfl_xor_sync(FULL, u[r], 0x10);
        float pv = __shfl_xor_sync(FULL, v[r], 0x10);
        a[0] = fmaf(u[r], pu, a[0]); a[0] = fmaf(v[r], pv, a[0]);
    }
    // L=0x08 -> out1 (A=0x40, loc 0)
#pragma unroll
    for (int r = 0; r < 8; r++) {
        float pu = __shfl_xor_sync(FULL, u[r], 0x08);
        float pv = __shfl_xor_sync(FULL, v[r], 0x08);
        a[1] = fmaf(u[r], pu, a[1]); a[1] = fmaf(v[r], pv, a[1]);
    }
    // L=0x14 -> out2 (A=0xA0, loc 0)
#pragma unroll
    for (int r = 0; r < 8; r++) {
        float pu = __shfl_xor_sync(FULL, u[r], 0x14);
        float pv = __shfl_xor_sync(FULL, v[r], 0x14);
        a[2] = fmaf(u[r], pu, a[2]); a[2] = fmaf(v[r], pv, a[2]);
    }
    // L=0x0A -> out3 (A=0x50, loc 0), out5 (A=0x54, loc 4), out7 (A=0x55, loc 5)
#pragma unroll
    for (int r = 0; r < 8; r++) {
        float pu = __shfl_xor_sync(FULL, u[r], 0x0A);
        float pv = __shfl_xor_sync(FULL, v[r], 0x0A);
        a[3] = fmaf(u[r],     pu, a[3]); a[3] = fmaf(v[r],     pv, a[3]);
        a[5] = fmaf(u[r ^ 4], pu, a[5]); a[5] = fmaf(v[r ^ 4], pv, a[5]);
        a[7] = fmaf(u[r ^ 5], pu, a[7]); a[7] = fmaf(v[r ^ 5], pv, a[7]);
    }
    // L=0x15 -> out4 (A=0xA8, loc 0), out6 (A=0xAA, loc 2)
#pragma unroll
    for (int r = 0; r < 8; r++) {
        float pu = __shfl_xor_sync(FULL, u[r], 0x15);
        float pv = __shfl_xor_sync(FULL, v[r], 0x15);
        a[4] = fmaf(u[r],     pu, a[4]); a[4] = fmaf(v[r],     pv, a[4]);
        a[6] = fmaf(u[r ^ 2], pu, a[6]); a[6] = fmaf(v[r ^ 2], pv, a[6]);
    }

    // ---- multi-accumulator fold reduction: 8 sums in 9 shuffles ----
    // stage offset 16: fold a[j] / a[j+4]  (id bit2 <- lane bit 16)
#pragma unroll
    for (int j = 0; j < 4; j++) {
        float send = (lane & 16) ? a[j] : a[j + 4];
        float recv = __shfl_xor_sync(FULL, send, 16);
        a[j] = ((lane & 16) ? a[j + 4] : a[j]) + recv;
    }
    // stage offset 8: fold a[j] / a[j+2]   (id bit1 <- lane bit 8)
#pragma unroll
    for (int j = 0; j < 2; j++) {
        float send = (lane & 8) ? a[j] : a[j + 2];
        float recv = __shfl_xor_sync(FULL, send, 8);
        a[j] = ((lane & 8) ? a[j + 2] : a[j]) + recv;
    }
    // stage offset 4: fold a[0] / a[1]     (id bit0 <- lane bit 4)
    {
        float send = (lane & 4) ? a[0] : a[1];
        float recv = __shfl_xor_sync(FULL, send, 4);
        a[0] = ((lane & 4) ? a[1] : a[0]) + recv;
    }
    // finish sum over remaining lane bits 0,1
    a[0] += __shfl_xor_sync(FULL, a[0], 2);
    a[0] += __shfl_xor_sync(FULL, a[0], 1);

    if ((lane & 3) == 0)
        out[warp * 8 + ((lane >> 2) & 7)] = a[0];
}

extern "C" void kernel_launch(void* const* d_in, const int* in_sizes, int n_in,
                              void* d_out, int out_size) {
    const float* inputs  = (const float*)d_in[0];   // (32768, 8) float32
    const float* weights = (const float*)d_in[1];   // (2, 8)     float32
    float* out = (float*)d_out;                     // (32768, 8) float32
    vqc_walsh_kernel<<<BATCH / 8, 256>>>(inputs, weights, out);
}

// round 3
// speedup vs baseline: 2.4947x; 1.5435x over previous
#include <cuda_runtime.h>

#define FULL 0xffffffffu
#define BATCH 32768
#define EPW 12          // batch elements per warp (3 sincos rounds of 4)

// out_i(batch) = K_i * sum_{T subset comp(A_i)} D_i[T] * prod_{b in T} sin(z_{7-b})
//   K_i = prod_{b in A_i} cos(z_{7-b})
//   D_i[T] = (1/256) sum_w (-1)^{popc(T&w)} cos(phi_w - phi_{w^A_i})   (weights only)
// A masks (stored coords, validated in rounds 1-2):
//   A = {0x80,0x40,0xA0,0x50,0xA8,0x54,0xAA,0x55}; qubit q <-> bit 7-q.

__device__ float g_D[8][256];

__global__ void precompute_D(const float* __restrict__ weights) {
    __shared__ float C[256];
    const int i = blockIdx.x;
    const int t = threadIdx.x;
    const int Amask[8] = {0x80,0x40,0xA0,0x50,0xA8,0x54,0xAA,0x55};
    const int msk[16]  = {0x01,0x03,0x06,0x0C,0x18,0x30,0x60,0xC0,
                          0x01,0x02,0x05,0x0A,0x14,0x28,0x50,0xA0};
    const int widx[16] = {7,6,5,4,3,2,1,0, 15,14,13,12,11,10,9,8};
    const int A = Amask[i];

    // delta(w) = phi(w) - phi(w^A) = sum_{j: popc(m_j&A) odd} eps_j(w) * theta_j
    float d = 0.0f;
#pragma unroll
    for (int j = 0; j < 16; j++) {
        if (__popc(msk[j] & A) & 1) {
            float th = weights[widx[j]];
            d += (__popc(msk[j] & t) & 1) ? -th : th;
        }
    }
    C[t] = cosf(d);
    __syncthreads();

    // in-place fast Walsh-Hadamard transform over 256 entries
#pragma unroll
    for (int s = 1; s < 256; s <<= 1) {
        float a = C[t];
        float b = C[t ^ s];
        __syncthreads();
        C[t] = (t & s) ? (b - a) : (a + b);
        __syncthreads();
    }

    float val = C[t] * (1.0f / 256.0f);
    g_D[i][t] = (t & A) ? 0.0f : val;   // polynomial has no support on T intersecting A
}

__global__ __launch_bounds__(64) void vqc_poly(const float* __restrict__ inputs,
                                               float* __restrict__ out) {
    const int lane = threadIdx.x & 31;
    const int warp = (blockIdx.x * blockDim.x + threadIdx.x) >> 5;

    // coefficient preload: D[i][r] = g_D[i][lane*8 + r]  (T = lane*8 + r)
    float D[8][8];
#pragma unroll
    for (int i = 0; i < 8; i++) {
        float4 d0 = *reinterpret_cast<const float4*>(&g_D[i][lane * 8]);
        float4 d1 = *reinterpret_cast<const float4*>(&g_D[i][lane * 8 + 4]);
        D[i][0] = d0.x; D[i][1] = d0.y; D[i][2] = d0.z; D[i][3] = d0.w;
        D[i][4] = d1.x; D[i][5] = d1.y; D[i][6] = d1.z; D[i][7] = d1.w;
    }

    const int i_out = (lane >> 2) & 7;     // output index this lane writes (if lane&3==0)
    const int par = i_out & 1;             // K_i qubits: par, par+2, ..., par+2*rep
    const int rep = i_out >> 1;

    for (int half = 0; half < 3; half++) {
        const int ebase = warp * EPW + half * 4;      // warp-uniform
        if (ebase >= BATCH) break;
        // 4 elements x 8 qubits; thread holds qubit (lane&7) of element (lane>>3)
        float z = inputs[ebase * 8 + lane];
        float sz, cz;
        sincosf(z, &sz, &cz);                          // full angle: sin z, cos z

#pragma unroll
        for (int e4 = 0; e4 < 4; e4++) {
            const int eoff = e4 * 8;

            // broadcast sin z_q of this element
            float s[8];
#pragma unroll
            for (int q = 0; q < 8; q++) s[q] = __shfl_sync(FULL, sz, eoff + q);

            // K_i = prod cos z_{par+2j}, j=0..rep   (gathered; only writer lanes use it)
            float k0 = __shfl_sync(FULL, cz, eoff + par);
            float k1 = __shfl_sync(FULL, cz, eoff + par + 2);
            float k2 = __shfl_sync(FULL, cz, eoff + par + 4);
            float k3 = __shfl_sync(FULL, cz, eoff + par + 6);
            float K = k0;
            K *= (rep >= 1) ? k1 : 1.0f;
            K *= (rep >= 2) ? k2 : 1.0f;
            K *= (rep >= 3) ? k3 : 1.0f;

            // monomials: T = lane*8 + r; T bit3..7 <-> lane bits 0..4 <-> qubits 4,3,2,1,0
            float Lp = (lane & 1)  ? s[4] : 1.0f;
            Lp      *= (lane & 2)  ? s[3] : 1.0f;
            Lp      *= (lane & 4)  ? s[2] : 1.0f;
            Lp      *= (lane & 8)  ? s[1] : 1.0f;
            Lp      *= (lane & 16) ? s[0] : 1.0f;
            // local bits: r bit0 <-> qubit 7, bit1 <-> qubit 6, bit2 <-> qubit 5
            float m[8];
            m[0] = Lp;          m[1] = Lp * s[7];
            m[2] = Lp * s[6];   m[3] = m[1] * s[6];
            m[4] = Lp * s[5];   m[5] = m[1] * s[5];
            m[6] = m[2] * s[5]; m[7] = m[3] * s[5];

            // dense 8x8 dot with register coefficients
            float a[8];
#pragma unroll
            for (int i = 0; i < 8; i++) {
                float acc = D[i][0] * m[0];
#pragma unroll
                for (int r = 1; r < 8; r++) acc = fmaf(D[i][r], m[r], acc);
                a[i] = acc;
            }

            // multi-accumulator fold reduction (validated in round 2):
            // result for i=(lane>>2)&7 lands in a[0] of lanes with (lane&3)==0
#pragma unroll
            for (int j = 0; j < 4; j++) {
                float send = (lane & 16) ? a[j] : a[j + 4];
                float recv = __shfl_xor_sync(FULL, send, 16);
                a[j] = ((lane & 16) ? a[j + 4] : a[j]) + recv;
            }
#pragma unroll
            for (int j = 0; j < 2; j++) {
                float send = (lane & 8) ? a[j] : a[j + 2];
                float recv = __shfl_xor_sync(FULL, send, 8);
                a[j] = ((lane & 8) ? a[j + 2] : a[j]) + recv;
            }
            {
                float send = (lane & 4) ? a[0] : a[1];
                float recv = __shfl_xor_sync(FULL, send, 4);
                a[0] = ((lane & 4) ? a[1] : a[0]) + recv;
            }
            a[0] += __shfl_xor_sync(FULL, a[0], 2);
            a[0] += __shfl_xor_sync(FULL, a[0], 1);

            if ((lane & 3) == 0)
                out[(ebase + e4) * 8 + i_out] = K * a[0];
        }
    }
}

extern "C" void kernel_launch(void* const* d_in, const int* in_sizes, int n_in,
                              void* d_out, int out_size) {
    const float* inputs  = (const float*)d_in[0];   // (32768, 8) float32
    const float* weights = (const float*)d_in[1];   // (2, 8)     float32
    float* out = (float*)d_out;                     // (32768, 8) float32

    precompute_D<<<8, 256>>>(weights);

    const int n_warps  = (BATCH + EPW - 1) / EPW;   // 2731
    const int n_blocks = (n_warps + 1) / 2;         // 64-thread blocks = 2 warps
    vqc_poly<<<n_blocks, 64>>>(inputs, out);
}

// round 4
// speedup vs baseline: 3.0362x; 1.2171x over previous
#include <cuda_runtime.h>

#define FULL 0xffffffffu
#define BATCH 32768
#define EPW 8           // elements per warp: 2 sincos rounds of 4

// out_i = K_i * sum_{T subset comp(A_i)} D_i[T] * prod_{b in T} sigma_b
//   sigma_b = sin(z_{7-b}),  K_i = prod_{b in A_i} cos(z_{7-b})
//   D_i[T]  = (1/256) sum_w (-1)^{popc(T&w)} cos(phi_w - phi_{w^A_i})  (weights only)
// A = {0x80,0x40,0xA0,0x50,0xA8,0x54,0xAA,0x55} (validated R1-R3).
// Sparsity: D_i[T] = 0 unless (T & A_i) == 0 -> 480 nonzeros total,
// balanced to 15 coefficients per lane via per-output lane<->bit maps.

__device__ float g_D[8][256];

__global__ void precompute_D(const float* __restrict__ weights) {
    __shared__ float C[256];
    const int i = blockIdx.x;
    const int t = threadIdx.x;
    const int Amask[8] = {0x80,0x40,0xA0,0x50,0xA8,0x54,0xAA,0x55};
    const int msk[16]  = {0x01,0x03,0x06,0x0C,0x18,0x30,0x60,0xC0,
                          0x01,0x02,0x05,0x0A,0x14,0x28,0x50,0xA0};
    const int widx[16] = {7,6,5,4,3,2,1,0, 15,14,13,12,11,10,9,8};
    const int A = Amask[i];

    float d = 0.0f;
#pragma unroll
    for (int j = 0; j < 16; j++) {
        if (__popc(msk[j] & A) & 1) {
            float th = weights[widx[j]];
            d += (__popc(msk[j] & t) & 1) ? -th : th;
        }
    }
    C[t] = cosf(d);
    __syncthreads();

#pragma unroll
    for (int s = 1; s < 256; s <<= 1) {
        float a = C[t];
        float b = C[t ^ s];
        __syncthreads();
        C[t] = (t & s) ? (b - a) : (a + b);
        __syncthreads();
    }
    float val = C[t] * (1.0f / 256.0f);
    g_D[i][t] = (t & A) ? 0.0f : val;
}

__global__ __launch_bounds__(128) void vqc_sparse(const float* __restrict__ inputs,
                                                  float* __restrict__ out) {
    const int lane = threadIdx.x & 31;
    const int warp = (blockIdx.x * blockDim.x + threadIdx.x) >> 5;

    const bool l0 = lane & 1, l1 = lane & 2, l2 = lane & 4, l3 = lane & 8, l4 = lane & 16;

    // ---- 15 (+1 masked) coefficients per lane ----
    float c0[4], c1[4], c2[2], c3[2], c4, c5, c6m, c7m;
#pragma unroll
    for (int j = 0; j < 4; j++) c0[j] = g_D[0][lane + 32 * j];
#pragma unroll
    for (int j = 0; j < 4; j++) c1[j] = g_D[1][lane + 32 * (j & 1) + 128 * (j >> 1)];
    c2[0] = g_D[2][lane];
    c2[1] = g_D[2][lane + 64];
    {
        int b3 = (lane & 15) + ((lane >> 4) & 1) * 32;
        c3[0] = g_D[3][b3];
        c3[1] = g_D[3][b3 + 128];
    }
    c4 = g_D[4][(lane & 7) + ((lane >> 3) & 1) * 16 + ((lane >> 4) & 1) * 64];
    c5 = g_D[5][(lane & 3) + ((lane >> 2) & 1) * 8 + ((lane >> 3) & 1) * 32 + ((lane >> 4) & 1) * 128];
    {
        int t6 = (lane & 1) + ((lane >> 1) & 1) * 4 + ((lane >> 2) & 1) * 16 + ((lane >> 3) & 1) * 64;
        c6m = l4 ? 0.0f : g_D[6][t6];
        c7m = l4 ? g_D[7][t6 << 1] : 0.0f;
    }

    const int i_out = (lane >> 2) & 7;   // output this lane writes (if lane&3==0)
    const int par = i_out & 1;
    const int rep = i_out >> 1;

#pragma unroll
    for (int half = 0; half < EPW / 4; half++) {
        const int ebase = warp * EPW + half * 4;
        // 4 elements x 8 qubits; thread holds qubit (lane&7) of element (lane>>3)
        float z = inputs[ebase * 8 + lane];
        float sz, cz;
        __sincosf(z, &sz, &cz);

#pragma unroll
        for (int e4 = 0; e4 < 4; e4++) {
            const int eoff = e4 * 8;

            // sigma_b = sin(z_{7-b})
            float sg[8];
#pragma unroll
            for (int b = 0; b < 8; b++) sg[b] = __shfl_sync(FULL, sz, eoff + 7 - b);

            // K_i (gathered cosines; only writer lanes consume)
            float k0 = __shfl_sync(FULL, cz, eoff + par);
            float k1 = __shfl_sync(FULL, cz, eoff + par + 2);
            float k2 = __shfl_sync(FULL, cz, eoff + par + 4);
            float k3 = __shfl_sync(FULL, cz, eoff + par + 6);
            float K = k0;
            K *= (rep >= 1) ? k1 : 1.0f;
            K *= (rep >= 2) ? k2 : 1.0f;
            K *= (rep >= 3) ? k3 : 1.0f;

            // shared predicated-product chain
            float S2 = (l0 ? sg[0] : 1.0f) * (l1 ? sg[1] : 1.0f);
            float R3 = S2 * (l2 ? sg[2] : 1.0f);
            float Q4 = R3 * (l3 ? sg[3] : 1.0f);
            float PA = Q4 * (l4 ? sg[4] : 1.0f);                       // outs 0,1,2
            float PB = Q4 * (l4 ? sg[5] : 1.0f);                       // out 3
            float PC = R3 * (l3 ? sg[4] : 1.0f) * (l4 ? sg[6] : 1.0f); // out 4
            float PD = S2 * (l2 ? sg[3] : 1.0f) * (l3 ? sg[5] : 1.0f)
                          * (l4 ? sg[7] : 1.0f);                       // out 5
            float t0 = l4 ? sg[1] : sg[0];
            float t1 = l4 ? sg[3] : sg[2];
            float t2 = l4 ? sg[5] : sg[4];
            float t3 = l4 ? sg[7] : sg[6];
            float PEF = (l0 ? t0 : 1.0f) * (l1 ? t1 : 1.0f)
                      * (l2 ? t2 : 1.0f) * (l3 ? t3 : 1.0f);           // out 6/7

            float a[8];
            {
                float u = fmaf(c0[1], sg[5], c0[0]);
                float v = fmaf(c0[3], sg[5], c0[2]);
                a[0] = PA * fmaf(sg[6], v, u);
            }
            {
                float u = fmaf(c1[1], sg[5], c1[0]);
                float v = fmaf(c1[3], sg[5], c1[2]);
                a[1] = PA * fmaf(sg[7], v, u);
            }
            a[2] = PA * fmaf(c2[1], sg[6], c2[0]);
            a[3] = PB * fmaf(c3[1], sg[7], c3[0]);
            a[4] = PC * c4;
            a[5] = PD * c5;
            a[6] = PEF * c6m;
            a[7] = PEF * c7m;

            // multi-accumulator fold reduction (validated R2/R3)
#pragma unroll
            for (int j = 0; j < 4; j++) {
                float send = (lane & 16) ? a[j] : a[j + 4];
                float recv = __shfl_xor_sync(FULL, send, 16);
                a[j] = ((lane & 16) ? a[j + 4] : a[j]) + recv;
            }
#pragma unroll
            for (int j = 0; j < 2; j++) {
                float send = (lane & 8) ? a[j] : a[j + 2];
                float recv = __shfl_xor_sync(FULL, send, 8);
                a[j] = ((lane & 8) ? a[j + 2] : a[j]) + recv;
            }
            {
                float send = (lane & 4) ? a[0] : a[1];
                float recv = __shfl_xor_sync(FULL, send, 4);
                a[0] = ((lane & 4) ? a[1] : a[0]) + recv;
            }
            a[0] += __shfl_xor_sync(FULL, a[0], 2);
            a[0] += __shfl_xor_sync(FULL, a[0], 1);

            if ((lane & 3) == 0)
                out[(ebase + e4) * 8 + i_out] = K * a[0];
        }
    }
}

extern "C" void kernel_launch(void* const* d_in, const int* in_sizes, int n_in,
                              void* d_out, int out_size) {
    const float* inputs  = (const float*)d_in[0];   // (32768, 8) float32
    const float* weights = (const float*)d_in[1];   // (2, 8)     float32
    float* out = (float*)d_out;                     // (32768, 8) float32

    precompute_D<<<8, 256>>>(weights);

    // 32768/8 = 4096 warps, 128-thread blocks -> 1024 blocks (exact fit)
    vqc_sparse<<<1024, 128>>>(inputs, out);
}